// round 4
// baseline (speedup 1.0000x reference)
#include <cuda_runtime.h>

typedef unsigned long long u64;

#define TW 32
#define TH 64
#define HALO 5
#define RW (TW + 2*HALO)      // 42
#define RH (TH + 2*HALO)      // 74
#define NT 256
#define IMG 512
#define PLANE (IMG*IMG)
#define RSTRIDE 46            // padded raw row stride (floats), kills bank conflicts
#define CH 20                 // raw chunk rows

#define SSIM_C1 0.0001f
#define SSIM_C2 0.0009f

#define HBN (RH*TW)           // 2368 floats per hb plane
// smem: x/y raw chunk planes + 5 scalar hb planes
#define SMEM_BYTES ((2*CH*RSTRIDE + 5*HBN)*4)   // 54720 -> 4 CTAs/SM

__device__ __forceinline__ u64 pack2(float a, float b) {
    u64 r; asm("mov.b64 %0,{%1,%2};" : "=l"(r) : "f"(a), "f"(b)); return r;
}
__device__ __forceinline__ void unpack2(u64 v, float& a, float& b) {
    asm("mov.b64 {%0,%1},%2;" : "=f"(a), "=f"(b) : "l"(v));
}
__device__ __forceinline__ u64 fma2(u64 a, u64 b, u64 c) {
    u64 r; asm("fma.rn.f32x2 %0,%1,%2,%3;" : "=l"(r) : "l"(a), "l"(b), "l"(c)); return r;
}
__device__ __forceinline__ u64 mul2(u64 a, u64 b) {
    u64 r; asm("mul.rn.f32x2 %0,%1,%2;" : "=l"(r) : "l"(a), "l"(b)); return r;
}

// 11-tap gaussian, sigma=1.5, normalized; symmetric
__device__ __forceinline__ constexpr float wk(int k) {
    constexpr float W6[6] = { 0.00102838f, 0.00759876f, 0.03600077f,
                              0.10936078f, 0.21300553f, 0.26601171f };
    return W6[k < 6 ? k : 10 - k];
}

__global__ void __launch_bounds__(NT, 4)
ssim_kernel(const float* __restrict__ x, const float* __restrict__ y,
            float* __restrict__ out)
{
    extern __shared__ float smem[];
    float* xpl = smem;                      // CH*RSTRIDE
    float* ypl = smem + CH*RSTRIDE;
    float* hb  = smem + 2*CH*RSTRIDE;       // 5 planes of HBN floats

    const int tid   = threadIdx.x;
    const int bx    = blockIdx.x;
    const int by    = blockIdx.y;
    const int plane = blockIdx.z;

    const float* __restrict__ xp = x + (size_t)plane * PLANE;
    const float* __restrict__ yp = y + (size_t)plane * PLANE;

    const int gx0 = bx * TW - HALO;
    const int gy0 = by * TH - HALO;

    u64 W2[6];
    #pragma unroll
    for (int k = 0; k < 6; ++k) W2[k] = pack2(wk(k), wk(k));

    const bool interior = (gx0 >= 0) & (gy0 >= 0) &
                          (gx0 + RW <= IMG) & (gy0 + RH <= IMG);

    // ============ Stages 1+2 fused, chunked over raw rows =================
    for (int cb = 0; cb < RH; cb += CH) {
        const int nrows = (RH - cb) < CH ? (RH - cb) : CH;

        // ---- load raw chunk (coalesced gmem -> smem scalar planes) ----
        if (interior) {
            for (int i = tid; i < nrows * RW; i += NT) {
                int r = i / RW;
                int c = i - r * RW;
                int off = (gy0 + cb + r) * IMG + (gx0 + c);
                xpl[r*RSTRIDE + c] = __ldg(xp + off);
                ypl[r*RSTRIDE + c] = __ldg(yp + off);
            }
        } else {
            for (int i = tid; i < nrows * RW; i += NT) {
                int r = i / RW;
                int c = i - r * RW;
                int gr = gy0 + cb + r, gc = gx0 + c;
                float xv = 0.f, yv = 0.f;
                if ((unsigned)gr < (unsigned)IMG && (unsigned)gc < (unsigned)IMG) {
                    int off = gr * IMG + gc;
                    xv = __ldg(xp + off);
                    yv = __ldg(yp + off);
                }
                xpl[r*RSTRIDE + c] = xv;
                ypl[r*RSTRIDE + c] = yv;
            }
        }
        __syncthreads();

        // ---- horizontal 11-tap, packed column pairs, 4 cols/thread ----
        for (int t = tid; t < nrows * 8; t += NT) {
            const int r = t >> 3;
            const int g = (t & 7) * 4;
            const float* xr = xpl + r*RSTRIDE + g;
            const float* yr = ypl + r*RSTRIDE + g;

            u64 A0=0,A1=0,A2=0,A3=0,A4=0;   // cols {g, g+1}
            u64 B0=0,B1=0,B2=0,B3=0,B4=0;   // cols {g+2, g+3}

#define PROC(J, XA, XB, YA, YB) do {                                   \
            u64 X2 = pack2((XA), (XB));                                \
            u64 Y2 = pack2((YA), (YB));                                \
            u64 XX = mul2(X2, X2);                                     \
            u64 YY = mul2(Y2, Y2);                                     \
            u64 XY = mul2(X2, Y2);                                     \
            if ((J) <= 10) {                                           \
                u64 wv = W2[(J) < 6 ? (J) : 10 - (J)];                 \
                A0 = fma2(X2, wv, A0); A1 = fma2(Y2, wv, A1);          \
                A2 = fma2(XX, wv, A2); A3 = fma2(YY, wv, A3);          \
                A4 = fma2(XY, wv, A4);                                 \
            }                                                          \
            if ((J) >= 2) {                                            \
                const int kk = (J) - 2;                                \
                u64 wv = W2[kk < 6 ? kk : 10 - kk];                    \
                B0 = fma2(X2, wv, B0); B1 = fma2(Y2, wv, B1);          \
                B2 = fma2(XX, wv, B2); B3 = fma2(YY, wv, B3);          \
                B4 = fma2(XY, wv, B4);                                 \
            }                                                          \
        } while (0)

            float2 xc = *(const float2*)xr;
            float2 yc = *(const float2*)yr;
            #pragma unroll
            for (int m = 0; m < 7; ++m) {
                PROC(2*m, xc.x, xc.y, yc.x, yc.y);
                if (m < 6) {
                    float2 xn = *(const float2*)(xr + 2*m + 2);
                    float2 yn = *(const float2*)(yr + 2*m + 2);
                    PROC(2*m + 1, xc.y, xn.x, yc.y, yn.x);
                    xc = xn; yc = yn;
                }
            }
#undef PROC

            const int o = (cb + r) * TW + g;
            *(u64*)&hb[0*HBN + o] = A0;  *(u64*)&hb[0*HBN + o + 2] = B0;
            *(u64*)&hb[1*HBN + o] = A1;  *(u64*)&hb[1*HBN + o + 2] = B1;
            *(u64*)&hb[2*HBN + o] = A2;  *(u64*)&hb[2*HBN + o + 2] = B2;
            *(u64*)&hb[3*HBN + o] = A3;  *(u64*)&hb[3*HBN + o + 2] = B3;
            *(u64*)&hb[4*HBN + o] = A4;  *(u64*)&hb[4*HBN + o + 2] = B4;
        }
        __syncthreads();
    }

    // ============ Stage 3: vertical 11-tap, packed col pairs, 2 rows ======
    #pragma unroll
    for (int w = 0; w < 2; ++w) {
        const int task = tid + w * NT;        // 0..511
        const int cp = (task & 15) * 2;       // even col
        const int r0 = (task >> 4) * 2;       // 0..62 step 2

        u64 a0[2] = {0,0}, a1[2] = {0,0}, a2[2] = {0,0},
            a3[2] = {0,0}, a4[2] = {0,0};

        #pragma unroll
        for (int p = 0; p < 12; ++p) {
            const int idx = (r0 + p) * TW + cp;
            u64 h0 = *(const u64*)&hb[0*HBN + idx];
            u64 h1 = *(const u64*)&hb[1*HBN + idx];
            u64 h2 = *(const u64*)&hb[2*HBN + idx];
            u64 h3 = *(const u64*)&hb[3*HBN + idx];
            u64 h4 = *(const u64*)&hb[4*HBN + idx];
            #pragma unroll
            for (int i2 = 0; i2 < 2; ++i2) {
                const int k = p - i2;
                if (k >= 0 && k <= 10) {
                    u64 wv = W2[k < 6 ? k : 10 - k];
                    a0[i2] = fma2(h0, wv, a0[i2]);
                    a1[i2] = fma2(h1, wv, a1[i2]);
                    a2[i2] = fma2(h2, wv, a2[i2]);
                    a3[i2] = fma2(h3, wv, a3[i2]);
                    a4[i2] = fma2(h4, wv, a4[i2]);
                }
            }
        }

        float* op = out + (size_t)plane * PLANE
                        + (size_t)(by * TH + r0) * IMG
                        + bx * TW + cp;

        #pragma unroll
        for (int i2 = 0; i2 < 2; ++i2) {
            float m1a, m1b, m2a, m2b, xxa, xxb, yya, yyb, xya, xyb;
            unpack2(a0[i2], m1a, m1b);
            unpack2(a1[i2], m2a, m2b);
            unpack2(a2[i2], xxa, xxb);
            unpack2(a3[i2], yya, yyb);
            unpack2(a4[i2], xya, xyb);

            float m12a = m1a*m2a, m11a = m1a*m1a, m22a = m2a*m2a;
            float s12a = xya - m12a, s11a = xxa - m11a, s22a = yya - m22a;
            float numa = fmaf(2.f, m12a, SSIM_C1) * fmaf(2.f, s12a, SSIM_C2);
            float dena = (m11a + m22a + SSIM_C1) * (s11a + s22a + SSIM_C2);
            float ra = __fdividef(numa, dena);

            float m12b = m1b*m2b, m11b = m1b*m1b, m22b = m2b*m2b;
            float s12b = xyb - m12b, s11b = xxb - m11b, s22b = yyb - m22b;
            float numb = fmaf(2.f, m12b, SSIM_C1) * fmaf(2.f, s12b, SSIM_C2);
            float denb = (m11b + m22b + SSIM_C1) * (s11b + s22b + SSIM_C2);
            float rb = __fdividef(numb, denb);

            *(float2*)(op + (size_t)i2 * IMG) = make_float2(ra, rb);
        }
    }
}

extern "C" void kernel_launch(void* const* d_in, const int* in_sizes, int n_in,
                              void* d_out, int out_size)
{
    const float* x = (const float*)d_in[0];   // img_out  [16,3,512,512] f32
    const float* y = (const float*)d_in[1];   // img_target
    float* out = (float*)d_out;

    int planes = in_sizes[0] / PLANE;         // 48

    cudaFuncSetAttribute(ssim_kernel,
                         cudaFuncAttributeMaxDynamicSharedMemorySize,
                         SMEM_BYTES);

    dim3 grid(IMG / TW, IMG / TH, planes);    // (16, 8, 48)
    ssim_kernel<<<grid, NT, SMEM_BYTES>>>(x, y, out);
}

// round 5
// speedup vs baseline: 1.1722x; 1.1722x over previous
#include <cuda_runtime.h>

#define TW 32
#define TH 32
#define HALO 5
#define RW (TW + 2*HALO)      // 42
#define RH (TH + 2*HALO)      // 42
#define NT 256
#define IMG 512
#define PLANE (IMG*IMG)

#define SSIM_C1 0.0001f
#define SSIM_C2 0.0009f

// smem: float2 raw[RH*RW] (14112 B) + 5 hb planes [RH*TW] (26880 B) = 40992 B
#define RAW_N (RH*RW)
#define HB_N  (RH*TW)
#define SMEM_BYTES (RAW_N*8 + 5*HB_N*4)

// 11-tap gaussian, sigma=1.5, normalized; symmetric
__device__ __forceinline__ constexpr float wk(int k) {
    constexpr float W6[6] = { 0.00102838f, 0.00759876f, 0.03600077f,
                              0.10936078f, 0.21300553f, 0.26601171f };
    return W6[k < 6 ? k : 10 - k];
}

__global__ void __launch_bounds__(NT, 5)
ssim_kernel(const float* __restrict__ x, const float* __restrict__ y,
            float* __restrict__ out)
{
    extern __shared__ float smem[];
    float2* raw = (float2*)smem;            // RH*RW
    float*  hb  = smem + RAW_N*2;           // 5 * HB_N

    const int tid   = threadIdx.x;
    const int bx    = blockIdx.x;           // 0..15
    const int by    = blockIdx.y;           // 0..15
    const int plane = blockIdx.z;           // 0..47

    const float* __restrict__ xp = x + (size_t)plane * PLANE;
    const float* __restrict__ yp = y + (size_t)plane * PLANE;

    const int gx0 = bx * TW - HALO;
    const int gy0 = by * TH - HALO;

    // ---------------- Stage 1: gmem -> smem raw tile ----------------------
    const bool interior = (gx0 >= 0) & (gy0 >= 0) &
                          (gx0 + RW <= IMG) & (gy0 + RH <= IMG);
    if (interior) {
        #pragma unroll 4
        for (int i = tid; i < RAW_N; i += NT) {
            int r = i / RW;
            int c = i - r * RW;
            int off = (gy0 + r) * IMG + (gx0 + c);
            raw[i] = make_float2(__ldg(xp + off), __ldg(yp + off));
        }
    } else {
        #pragma unroll 4
        for (int i = tid; i < RAW_N; i += NT) {
            int r = i / RW;
            int c = i - r * RW;
            int gr = gy0 + r, gc = gx0 + c;
            float xv = 0.f, yv = 0.f;
            if ((unsigned)gr < (unsigned)IMG && (unsigned)gc < (unsigned)IMG) {
                int off = gr * IMG + gc;
                xv = __ldg(xp + off);
                yv = __ldg(yp + off);
            }
            raw[i] = make_float2(xv, yv);
        }
    }
    __syncthreads();

    // ---------------- Stage 2: horizontal 11-tap, 4-col register block ----
    // tasks: RH rows * 8 groups = 336
    for (int t = tid; t < RH * (TW/4); t += NT) {
        const int row = t >> 3;
        const int g   = (t & 7) * 4;
        const float2* rp = raw + row * RW + g;

        float a0[4] = {0,0,0,0}, a1[4] = {0,0,0,0}, a2[4] = {0,0,0,0},
              a3[4] = {0,0,0,0}, a4[4] = {0,0,0,0};

        #pragma unroll
        for (int p = 0; p < 14; ++p) {
            float2 v  = rp[p];
            float  xx = v.x * v.x;
            float  yy = v.y * v.y;
            float  xy = v.x * v.y;
            #pragma unroll
            for (int i2 = 0; i2 < 4; ++i2) {
                int k = p - i2;
                if (k >= 0 && k <= 10) {
                    a0[i2] = fmaf(v.x, wk(k), a0[i2]);
                    a1[i2] = fmaf(v.y, wk(k), a1[i2]);
                    a2[i2] = fmaf(xx,  wk(k), a2[i2]);
                    a3[i2] = fmaf(yy,  wk(k), a3[i2]);
                    a4[i2] = fmaf(xy,  wk(k), a4[i2]);
                }
            }
        }

        const int o = row * TW + g;
        *(float4*)&hb[0*HB_N + o] = make_float4(a0[0], a0[1], a0[2], a0[3]);
        *(float4*)&hb[1*HB_N + o] = make_float4(a1[0], a1[1], a1[2], a1[3]);
        *(float4*)&hb[2*HB_N + o] = make_float4(a2[0], a2[1], a2[2], a2[3]);
        *(float4*)&hb[3*HB_N + o] = make_float4(a3[0], a3[1], a3[2], a3[3]);
        *(float4*)&hb[4*HB_N + o] = make_float4(a4[0], a4[1], a4[2], a4[3]);
    }
    __syncthreads();

    // ---------------- Stage 3: vertical 11-tap, 4-row block, 1 task/thread
    {
        const int col = tid & 31;
        const int r0  = (tid >> 5) * 4;     // 8 segments * 4 rows = 32

        float b0[4] = {0,0,0,0}, b1[4] = {0,0,0,0}, b2[4] = {0,0,0,0},
              b3[4] = {0,0,0,0}, b4[4] = {0,0,0,0};

        const float* hcol = hb + col;
        #pragma unroll
        for (int p = 0; p < 14; ++p) {
            const int idx = (r0 + p) * TW;
            float h0 = hcol[0*HB_N + idx];
            float h1 = hcol[1*HB_N + idx];
            float h2 = hcol[2*HB_N + idx];
            float h3 = hcol[3*HB_N + idx];
            float h4 = hcol[4*HB_N + idx];
            #pragma unroll
            for (int i2 = 0; i2 < 4; ++i2) {
                int k = p - i2;
                if (k >= 0 && k <= 10) {
                    b0[i2] = fmaf(h0, wk(k), b0[i2]);
                    b1[i2] = fmaf(h1, wk(k), b1[i2]);
                    b2[i2] = fmaf(h2, wk(k), b2[i2]);
                    b3[i2] = fmaf(h3, wk(k), b3[i2]);
                    b4[i2] = fmaf(h4, wk(k), b4[i2]);
                }
            }
        }

        float* op = out + (size_t)plane * PLANE
                        + (size_t)(by * TH + r0) * IMG
                        + bx * TW + col;

        #pragma unroll
        for (int i2 = 0; i2 < 4; ++i2) {
            float mu1    = b0[i2];
            float mu2    = b1[i2];
            float mu1mu2 = mu1 * mu2;
            float mu1sq  = mu1 * mu1;
            float mu2sq  = mu2 * mu2;
            float s11    = b2[i2] - mu1sq;
            float s22    = b3[i2] - mu2sq;
            float s12    = b4[i2] - mu1mu2;
            float num = fmaf(2.f, mu1mu2, SSIM_C1) * fmaf(2.f, s12, SSIM_C2);
            float den = (mu1sq + mu2sq + SSIM_C1) * (s11 + s22 + SSIM_C2);
            op[(size_t)i2 * IMG] = __fdividef(num, den);
        }
    }
}

extern "C" void kernel_launch(void* const* d_in, const int* in_sizes, int n_in,
                              void* d_out, int out_size)
{
    const float* x = (const float*)d_in[0];   // img_out  [16,3,512,512] f32
    const float* y = (const float*)d_in[1];   // img_target
    float* out = (float*)d_out;

    int planes = in_sizes[0] / PLANE;         // 48

    cudaFuncSetAttribute(ssim_kernel,
                         cudaFuncAttributeMaxDynamicSharedMemorySize,
                         SMEM_BYTES);

    dim3 grid(IMG / TW, IMG / TH, planes);    // (16, 16, 48)
    ssim_kernel<<<grid, NT, SMEM_BYTES>>>(x, y, out);
}